// round 16
// baseline (speedup 1.0000x reference)
#include <cuda_runtime.h>
#include <cuda_fp16.h>
#include <cstdint>

// ScaledDotProductAttention B=8, S=2048, D=1024 fp32.
// R16: persistent fused kernel (V-transpose + GEMM1 + GEMM2) with atomic tile
// queue + readiness flags. Fix vs R15: tid0-only acquire spin (was 128-thread).

namespace {
constexpr int BN = 8, S_ = 2048, D_ = 1024;
constexpr float SCALE = 0.03125f;          // D^-0.5 (folded into Q convert)
constexpr float NEGV  = -1000000000.0f;

constexpr int TM = 128, TN = 128, TK = 64;
constexpr int NT = 128;
constexpr uint32_t BUF_B   = 16384;
constexpr uint32_t STAGE_B = 2 * BUF_B;
constexpr uint32_t PIPE_B  = 3 * STAGE_B;                // 98304
constexpr uint32_t OFF_MASK = PIPE_B;                    // 512 B (128 floats)
constexpr uint32_t OFF_SUM  = PIPE_B + 512;              // 1024 B
constexpr uint32_t OFF_POP  = PIPE_B + 1536;             // 16 B
constexpr uint32_t SMEM_F   = PIPE_B + 1552;

constexpr int PH1_V = 512;                 // V units first
constexpr int PH1_TOTAL = PH1_V + 2048;    // + gemm1 tiles
constexpr int PH2_TOTAL = 1024;            // gemm2 tiles

// sync array indices
constexpr int SY_TIX1 = 0, SY_TIX2 = 1, SY_ROW0 = 2, SY_VC0 = 130, SY_N = 138;
}  // namespace

// ------------------------- scratch (device globals) -------------------------
__device__ __align__(128) __half g_qh[(size_t)BN * S_ * D_];
__device__ __align__(128) __half g_kh[(size_t)BN * S_ * D_];
__device__ __align__(128) __half g_vt[(size_t)BN * D_ * S_];   // V^T [b][d][s]
__device__ __align__(128) __half g_p [(size_t)BN * S_ * S_];   // unnormalized exp P~
__device__ __align__(128) float  g_ps[(size_t)BN * S_ * 16];   // row partial sums
__device__ unsigned int g_sync[SY_N];                          // queue + flags

// ------------------------------- helpers ------------------------------------
__device__ __forceinline__ uint32_t smem_u32(const void* p) {
    uint32_t a;
    asm("{ .reg .u64 t; cvta.to.shared.u64 t, %1; cvt.u32.u64 %0, t; }"
        : "=r"(a) : "l"(p));
    return a;
}
__device__ __forceinline__ unsigned int ld_acquire(const unsigned int* p) {
    unsigned int v;
    asm volatile("ld.acquire.gpu.global.u32 %0, [%1];" : "=r"(v) : "l"(p) : "memory");
    return v;
}

#define LDSM4(r, addr) \
    asm volatile("ldmatrix.sync.aligned.m8n8.x4.shared.b16 {%0,%1,%2,%3}, [%4];" \
        : "=r"((r)[0]), "=r"((r)[1]), "=r"((r)[2]), "=r"((r)[3]) : "r"(addr))

#define MMA_F16(d, a, b0, b1) \
    asm volatile("mma.sync.aligned.m16n8k16.row.col.f32.f16.f16.f32 " \
        "{%0,%1,%2,%3}, {%4,%5,%6,%7}, {%8,%9}, {%0,%1,%2,%3};" \
        : "+f"((d)[0]), "+f"((d)[1]), "+f"((d)[2]), "+f"((d)[3]) \
        : "r"((a)[0]), "r"((a)[1]), "r"((a)[2]), "r"((a)[3]), "r"(b0), "r"(b1))

#define CP_ASYNC16(dst, src) \
    asm volatile("cp.async.cg.shared.global [%0], [%1], 16;" :: "r"(dst), "l"(src))
#define CP_COMMIT()  asm volatile("cp.async.commit_group;" ::: "memory")
#define CP_WAIT(n)   asm volatile("cp.async.wait_group %0;" :: "n"(n) : "memory")

__device__ __forceinline__ uint2 pack4(const uint16_t* h) {
    return make_uint2((uint32_t)h[0] | ((uint32_t)h[1] << 16),
                      (uint32_t)h[2] | ((uint32_t)h[3] << 16));
}

// --------------------- convert kernel: Q*SCALE, K -> fp16 --------------------
__global__ void __launch_bounds__(256) conv_qk_kernel(
    const float* __restrict__ q, const float* __restrict__ k) {
    const int bx = blockIdx.x;
    const bool isq = (bx < 8192);
    const float* src = isq ? q : k;
    __half* dst = isq ? g_qh : g_kh;
    const float sc = isq ? SCALE : 1.0f;
    size_t e0 = ((size_t)(bx & 8191) * 256 + threadIdx.x) * 8;
    float4 v0 = *reinterpret_cast<const float4*>(src + e0);
    float4 v1 = *reinterpret_cast<const float4*>(src + e0 + 4);
    uint16_t h[8];
    h[0] = __half_as_ushort(__float2half_rn(v0.x * sc));
    h[1] = __half_as_ushort(__float2half_rn(v0.y * sc));
    h[2] = __half_as_ushort(__float2half_rn(v0.z * sc));
    h[3] = __half_as_ushort(__float2half_rn(v0.w * sc));
    h[4] = __half_as_ushort(__float2half_rn(v1.x * sc));
    h[5] = __half_as_ushort(__float2half_rn(v1.y * sc));
    h[6] = __half_as_ushort(__float2half_rn(v1.z * sc));
    h[7] = __half_as_ushort(__float2half_rn(v1.w * sc));
    uint2 lo = pack4(h), hi = pack4(h + 4);
    *reinterpret_cast<uint4*>(dst + e0) = make_uint4(lo.x, lo.y, hi.x, hi.y);
}

// ------------------------------ tile workers --------------------------------
__device__ __forceinline__ void v_unit(char* smg, int tid, int unit,
                                       const float* __restrict__ v) {
    float (*tile)[65] = (float(*)[65])smg;
    const int b = unit >> 6;
    const int rest0 = unit & 63;
    const int i0 = tid >> 4, j4 = (tid & 15) * 4;
#pragma unroll 1
    for (int u = 0; u < 8; ++u) {
        const int rest = rest0 * 8 + u;
        const int st = rest >> 4;
        const int dt = rest & 15;
#pragma unroll
        for (int r = 0; r < 8; ++r) {
            int i = i0 + r * 8;
            float4 val = *reinterpret_cast<const float4*>(
                v + ((size_t)b * S_ + st * 64 + i) * D_ + dt * 64 + j4);
            tile[i][j4 + 0] = val.x; tile[i][j4 + 1] = val.y;
            tile[i][j4 + 2] = val.z; tile[i][j4 + 3] = val.w;
        }
        __syncthreads();
#pragma unroll
        for (int r = 0; r < 8; ++r) {
            int dl_ = i0 + r * 8;
            uint16_t h[4];
#pragma unroll
            for (int c = 0; c < 4; ++c)
                h[c] = __half_as_ushort(__float2half_rn(tile[j4 + c][dl_]));
            size_t off = ((size_t)b * D_ + dt * 64 + dl_) * S_ + st * 64 + j4;
            *reinterpret_cast<uint2*>(g_vt + off) = pack4(h);
        }
        __syncthreads();
    }
    if (tid == 0) {
        __threadfence();
        atomicAdd(&g_sync[SY_VC0 + b], 1u);
    }
}

__device__ __forceinline__ void gemm1_tile(char* smg, uint32_t smb, int tid,
                                           int mt, int nt, int b,
                                           const __half* __restrict__ Ah,
                                           const __half* __restrict__ Bh,
                                           const float* __restrict__ mask) {
    float* smmask = (float*)(smg + OFF_MASK);
    float (*smsum)[2] = (float(*)[2])(smg + OFF_SUM);

    const int warp = tid >> 5, lane = tid & 31;
    const int wm = warp & 1, wn = warp >> 1;
    const int lrow = lane & 15;
    const int lh16 = (lane >> 4) << 4;
    const int r7 = (lane & 7) << 4;
    constexpr int NC = D_ / TK;  // 16

    const int drow = tid >> 3, cc = tid & 7;
    const uint32_t dstoff0 = (uint32_t)(drow * 128 + ((cc ^ (drow & 7)) << 4));
    const __half* gA = Ah + ((size_t)b * S_ + mt * TM + drow) * D_ + cc * 8;
    const __half* gB = Bh + ((size_t)b * S_ + nt * TN + drow) * D_ + cc * 8;

    smmask[tid] = mask[(size_t)b * S_ + nt * TN + tid] * NEGV;

    uint32_t sload = 0;
    auto issue = [&]() {
        uint32_t da = smb + sload + dstoff0;
#pragma unroll
        for (int i = 0; i < 8; ++i) {
            CP_ASYNC16(da + i * 2048,         gA + i * 16 * D_);
            CP_ASYNC16(da + BUF_B + i * 2048, gB + i * 16 * D_);
        }
        CP_COMMIT();
        gA += TK; gB += TK;
        sload += STAGE_B; if (sload == PIPE_B) sload = 0;
    };

    float acc[4][8][4];
#pragma unroll
    for (int i = 0; i < 4; ++i)
#pragma unroll
        for (int n = 0; n < 8; ++n)
#pragma unroll
            for (int r = 0; r < 4; ++r) acc[i][n][r] = 0.f;

    issue();
    issue();

    const uint32_t cA = (uint32_t)((wm * 64 + lrow) * 128);
    const uint32_t cB = (uint32_t)(BUF_B + (wn * 64 + lrow) * 128);

    uint32_t scomp = 0;
#pragma unroll 1
    for (int c = 0; c < NC; ++c) {
        if (c + 1 < NC) CP_WAIT(1);
        else            CP_WAIT(0);
        __syncthreads();
        if (c + 2 < NC) issue();

        const uint32_t uA0 = smb + scomp + cA;
        const uint32_t uB0 = smb + scomp + cB;
        scomp += STAGE_B; if (scomp == PIPE_B) scomp = 0;

        uint32_t ah[2][4][4], bh[2][4][4];
        {
            const uint32_t kxr0 = (uint32_t)(lh16 ^ r7);
#pragma unroll
            for (int i = 0; i < 4; ++i) LDSM4(ah[0][i], uA0 + i * 2048 + kxr0);
#pragma unroll
            for (int j = 0; j < 4; ++j) LDSM4(bh[0][j], uB0 + j * 2048 + kxr0);
        }
#pragma unroll
        for (int ks = 0; ks < 4; ++ks) {
            const int cur = ks & 1, nxt = cur ^ 1;
            if (ks < 3) {
                const uint32_t kxr = (uint32_t)(((ks + 1) * 32 + lh16) ^ r7);
#pragma unroll
                for (int i = 0; i < 4; ++i)
                    LDSM4(ah[nxt][i], uA0 + i * 2048 + kxr);
#pragma unroll
                for (int j = 0; j < 4; ++j)
                    LDSM4(bh[nxt][j], uB0 + j * 2048 + kxr);
            }
#pragma unroll
            for (int i = 0; i < 4; ++i)
#pragma unroll
                for (int n = 0; n < 8; ++n) {
                    int j = n >> 1, s = n & 1;
                    MMA_F16(acc[i][n], ah[cur][i], bh[cur][j][s], bh[cur][j][s + 2]);
                }
        }
    }

    const int rloc = wm * 64 + (lane >> 2);
    const int r0 = mt * TM + rloc;
    const int cl0 = wn * 64 + (lane & 3) * 2;
#pragma unroll
    for (int i = 0; i < 4; ++i) {
        float sum_lo = 0.f, sum_hi = 0.f;
#pragma unroll
        for (int n = 0; n < 8; ++n) {
            int cl = cl0 + n * 8;
            float mk0 = smmask[cl], mk1 = smmask[cl + 1];
            float e0 = __expf(acc[i][n][0] + mk0);
            float e1 = __expf(acc[i][n][1] + mk1);
            float e2 = __expf(acc[i][n][2] + mk0);
            float e3 = __expf(acc[i][n][3] + mk1);
            sum_lo += e0 + e1;
            sum_hi += e2 + e3;
            size_t rowa = (size_t)(b * S_ + r0 + i * 16) * S_ + nt * TN + cl;
            size_t rowb = rowa + (size_t)8 * S_;
            *reinterpret_cast<__half2*>(g_p + rowa) = __floats2half2_rn(e0, e1);
            *reinterpret_cast<__half2*>(g_p + rowb) = __floats2half2_rn(e2, e3);
        }
#pragma unroll
        for (int o = 1; o < 4; o <<= 1) {
            sum_lo += __shfl_xor_sync(~0u, sum_lo, o);
            sum_hi += __shfl_xor_sync(~0u, sum_hi, o);
        }
        if ((lane & 3) == 0) {
            smsum[rloc + i * 16][wn]     = sum_lo;
            smsum[rloc + i * 16 + 8][wn] = sum_hi;
        }
    }
    __syncthreads();
    g_ps[((size_t)(b * S_ + mt * TM + tid)) * 16 + nt] =
        smsum[tid][0] + smsum[tid][1];
    __syncthreads();
    if (tid == 0) {
        __threadfence();
        atomicAdd(&g_sync[SY_ROW0 + b * 16 + mt], 1u);
    }
}

__device__ __forceinline__ void gemm2_tile(char* smg, uint32_t smb, int tid,
                                           int mt, int nt, int b,
                                           float* __restrict__ Cp) {
    float* sminv = (float*)(smg + OFF_MASK);  // reuse mask slot: [128]

    // readiness: tid0 spins on row-group + V flags, then block-wide barrier.
    if (tid == 0) {
        const unsigned int* rowc = &g_sync[SY_ROW0 + b * 16 + mt];
        const unsigned int* vc   = &g_sync[SY_VC0 + b];
        while (ld_acquire(rowc) < 16u) __nanosleep(64);
        while (ld_acquire(vc) < 64u)   __nanosleep(64);
    }
    __syncthreads();

    const int warp = tid >> 5, lane = tid & 31;
    const int wm = warp & 1, wn = warp >> 1;
    const int lrow = lane & 15;
    const int lh16 = (lane >> 4) << 4;
    const int r7 = (lane & 7) << 4;
    constexpr int NC = S_ / TK;  // 32

    const int drow = tid >> 3, cc = tid & 7;
    const uint32_t dstoff0 = (uint32_t)(drow * 128 + ((cc ^ (drow & 7)) << 4));
    const __half* gA = g_p  + ((size_t)b * S_ + mt * TM + drow) * S_ + cc * 8;
    const __half* gB = g_vt + ((size_t)b * D_ + nt * TN + drow) * S_ + cc * 8;

    {
        const float* ps = g_ps + ((size_t)(b * S_ + mt * TM + tid)) * 16;
        float s = 0.f;
#pragma unroll
        for (int j = 0; j < 16; ++j) s += __ldcg(ps + j);
        sminv[tid] = 1.0f / s;
    }

    uint32_t sload = 0;
    auto issue = [&]() {
        uint32_t da = smb + sload + dstoff0;
#pragma unroll
        for (int i = 0; i < 8; ++i) {
            CP_ASYNC16(da + i * 2048,         gA + i * 16 * S_);
            CP_ASYNC16(da + BUF_B + i * 2048, gB + i * 16 * S_);
        }
        CP_COMMIT();
        gA += TK; gB += TK;
        sload += STAGE_B; if (sload == PIPE_B) sload = 0;
    };

    float acc[4][8][4];
#pragma unroll
    for (int i = 0; i < 4; ++i)
#pragma unroll
        for (int n = 0; n < 8; ++n)
#pragma unroll
            for (int r = 0; r < 4; ++r) acc[i][n][r] = 0.f;

    issue();
    issue();

    const uint32_t cA = (uint32_t)((wm * 64 + lrow) * 128);
    const uint32_t cB = (uint32_t)(BUF_B + (wn * 64 + lrow) * 128);

    uint32_t scomp = 0;
#pragma unroll 1
    for (int c = 0; c < NC; ++c) {
        if (c + 1 < NC) CP_WAIT(1);
        else            CP_WAIT(0);
        __syncthreads();
        if (c + 2 < NC) issue();

        const uint32_t uA0 = smb + scomp + cA;
        const uint32_t uB0 = smb + scomp + cB;
        scomp += STAGE_B; if (scomp == PIPE_B) scomp = 0;

        uint32_t ah[2][4][4], bh[2][4][4];
        {
            const uint32_t kxr0 = (uint32_t)(lh16 ^ r7);
#pragma unroll
            for (int i = 0; i < 4; ++i) LDSM4(ah[0][i], uA0 + i * 2048 + kxr0);
#pragma unroll
            for (int j = 0; j < 4; ++j) LDSM4(bh[0][j], uB0 + j * 2048 + kxr0);
        }
#pragma unroll
        for (int ks = 0; ks < 4; ++ks) {
            const int cur = ks & 1, nxt = cur ^ 1;
            if (ks < 3) {
                const uint32_t kxr = (uint32_t)(((ks + 1) * 32 + lh16) ^ r7);
#pragma unroll
                for (int i = 0; i < 4; ++i)
                    LDSM4(ah[nxt][i], uA0 + i * 2048 + kxr);
#pragma unroll
                for (int j = 0; j < 4; ++j)
                    LDSM4(bh[nxt][j], uB0 + j * 2048 + kxr);
            }
#pragma unroll
            for (int i = 0; i < 4; ++i)
#pragma unroll
                for (int n = 0; n < 8; ++n) {
                    int j = n >> 1, s = n & 1;
                    MMA_F16(acc[i][n], ah[cur][i], bh[cur][j][s], bh[cur][j][s + 2]);
                }
        }
    }

    const int rloc = wm * 64 + (lane >> 2);
    const int r0 = mt * TM + rloc;
    const int cl0 = wn * 64 + (lane & 3) * 2;
#pragma unroll
    for (int i = 0; i < 4; ++i) {
        float inv_lo = sminv[rloc + i * 16];
        float inv_hi = sminv[rloc + i * 16 + 8];
#pragma unroll
        for (int n = 0; n < 8; ++n) {
            int col = nt * TN + cl0 + n * 8;
            size_t rowa = (size_t)(b * S_ + r0 + i * 16) * D_ + col;
            size_t rowb = rowa + (size_t)8 * D_;
            *reinterpret_cast<float2*>(Cp + rowa) =
                make_float2(acc[i][n][0] * inv_lo, acc[i][n][1] * inv_lo);
            *reinterpret_cast<float2*>(Cp + rowb) =
                make_float2(acc[i][n][2] * inv_hi, acc[i][n][3] * inv_hi);
        }
    }
}

// ------------------------- fused persistent kernel ---------------------------
__global__ void __launch_bounds__(NT, 2)
attn_fused_kernel(const __half* __restrict__ Ah, const __half* __restrict__ Bh,
                  const float* __restrict__ mask, const float* __restrict__ v,
                  float* __restrict__ out) {
    extern __shared__ __align__(1024) char smg[];
    const uint32_t smb = smem_u32(smg);
    const int tid = threadIdx.x;
    volatile unsigned int* spop = (volatile unsigned int*)(smg + OFF_POP);

    // ---- phase 1: V units, then gemm1 tiles ----
    for (;;) {
        __syncthreads();                 // smem reuse guard + pop broadcast
        if (tid == 0) *spop = atomicAdd(&g_sync[SY_TIX1], 1u);
        __syncthreads();
        unsigned int t = *spop;
        if (t >= PH1_TOTAL) break;
        if (t < PH1_V) {
            v_unit(smg, tid, (int)t, v);
        } else {
            const int g = (int)t - PH1_V;
            const int rg = g >> 4, nt = g & 15;
            const int b = rg >> 4, mt = rg & 15;
            gemm1_tile(smg, smb, tid, mt, nt, b, Ah, Bh, mask);
        }
    }

    // ---- phase 2: gemm2 tiles ----
    for (;;) {
        __syncthreads();
        if (tid == 0) *spop = atomicAdd(&g_sync[SY_TIX2], 1u);
        __syncthreads();
        unsigned int t = *spop;
        if (t >= PH2_TOTAL) break;
        const int rg = (int)t >> 3, nt = (int)t & 7;
        const int b = rg >> 4, mt = rg & 15;
        gemm2_tile(smg, smb, tid, mt, nt, b, out);
    }
}

// --------------------------------- launch -----------------------------------
extern "C" void kernel_launch(void* const* d_in, const int* in_sizes, int n_in,
                              void* d_out, int out_size) {
    const float* q    = (const float*)d_in[0];
    const float* k    = (const float*)d_in[1];
    const float* v    = (const float*)d_in[2];
    const float* mask = (const float*)d_in[3];
    float* out = (float*)d_out;

    cudaFuncSetAttribute(attn_fused_kernel,
                         cudaFuncAttributeMaxDynamicSharedMemorySize, SMEM_F);

    __half *qh, *kh;
    void* syncp;
    cudaGetSymbolAddress((void**)&qh, g_qh);
    cudaGetSymbolAddress((void**)&kh, g_kh);
    cudaGetSymbolAddress(&syncp, g_sync);

    int nsm = 148;
    cudaDeviceGetAttribute(&nsm, cudaDevAttrMultiProcessorCount, 0);

    cudaMemsetAsync(syncp, 0, SY_N * sizeof(unsigned int));
    conv_qk_kernel<<<16384, 256>>>(q, k);
    attn_fused_kernel<<<2 * nsm, NT, SMEM_F>>>(qh, kh, mask, v, out);
}

// round 17
// speedup vs baseline: 1.0033x; 1.0033x over previous
#include <cuda_runtime.h>
#include <cuda_fp16.h>
#include <cstdint>

// ScaledDotProductAttention B=8, S=2048, D=1024 fp32.
// R16: persistent fused kernel (V-transpose + GEMM1 + GEMM2) with atomic tile
// queue + readiness flags. Fix vs R15: tid0-only acquire spin (was 128-thread).

namespace {
constexpr int BN = 8, S_ = 2048, D_ = 1024;
constexpr float SCALE = 0.03125f;          // D^-0.5 (folded into Q convert)
constexpr float NEGV  = -1000000000.0f;

constexpr int TM = 128, TN = 128, TK = 64;
constexpr int NT = 128;
constexpr uint32_t BUF_B   = 16384;
constexpr uint32_t STAGE_B = 2 * BUF_B;
constexpr uint32_t PIPE_B  = 3 * STAGE_B;                // 98304
constexpr uint32_t OFF_MASK = PIPE_B;                    // 512 B (128 floats)
constexpr uint32_t OFF_SUM  = PIPE_B + 512;              // 1024 B
constexpr uint32_t OFF_POP  = PIPE_B + 1536;             // 16 B
constexpr uint32_t SMEM_F   = PIPE_B + 1552;

constexpr int PH1_V = 512;                 // V units first
constexpr int PH1_TOTAL = PH1_V + 2048;    // + gemm1 tiles
constexpr int PH2_TOTAL = 1024;            // gemm2 tiles

// sync array indices
constexpr int SY_TIX1 = 0, SY_TIX2 = 1, SY_ROW0 = 2, SY_VC0 = 130, SY_N = 138;
}  // namespace

// ------------------------- scratch (device globals) -------------------------
__device__ __align__(128) __half g_qh[(size_t)BN * S_ * D_];
__device__ __align__(128) __half g_kh[(size_t)BN * S_ * D_];
__device__ __align__(128) __half g_vt[(size_t)BN * D_ * S_];   // V^T [b][d][s]
__device__ __align__(128) __half g_p [(size_t)BN * S_ * S_];   // unnormalized exp P~
__device__ __align__(128) float  g_ps[(size_t)BN * S_ * 16];   // row partial sums
__device__ unsigned int g_sync[SY_N];                          // queue + flags

// ------------------------------- helpers ------------------------------------
__device__ __forceinline__ uint32_t smem_u32(const void* p) {
    uint32_t a;
    asm("{ .reg .u64 t; cvta.to.shared.u64 t, %1; cvt.u32.u64 %0, t; }"
        : "=r"(a) : "l"(p));
    return a;
}
__device__ __forceinline__ unsigned int ld_acquire(const unsigned int* p) {
    unsigned int v;
    asm volatile("ld.acquire.gpu.global.u32 %0, [%1];" : "=r"(v) : "l"(p) : "memory");
    return v;
}

#define LDSM4(r, addr) \
    asm volatile("ldmatrix.sync.aligned.m8n8.x4.shared.b16 {%0,%1,%2,%3}, [%4];" \
        : "=r"((r)[0]), "=r"((r)[1]), "=r"((r)[2]), "=r"((r)[3]) : "r"(addr))

#define MMA_F16(d, a, b0, b1) \
    asm volatile("mma.sync.aligned.m16n8k16.row.col.f32.f16.f16.f32 " \
        "{%0,%1,%2,%3}, {%4,%5,%6,%7}, {%8,%9}, {%0,%1,%2,%3};" \
        : "+f"((d)[0]), "+f"((d)[1]), "+f"((d)[2]), "+f"((d)[3]) \
        : "r"((a)[0]), "r"((a)[1]), "r"((a)[2]), "r"((a)[3]), "r"(b0), "r"(b1))

#define CP_ASYNC16(dst, src) \
    asm volatile("cp.async.cg.shared.global [%0], [%1], 16;" :: "r"(dst), "l"(src))
#define CP_COMMIT()  asm volatile("cp.async.commit_group;" ::: "memory")
#define CP_WAIT(n)   asm volatile("cp.async.wait_group %0;" :: "n"(n) : "memory")

__device__ __forceinline__ uint2 pack4(const uint16_t* h) {
    return make_uint2((uint32_t)h[0] | ((uint32_t)h[1] << 16),
                      (uint32_t)h[2] | ((uint32_t)h[3] << 16));
}

// --------------------- convert kernel: Q*SCALE, K -> fp16 --------------------
__global__ void __launch_bounds__(256) conv_qk_kernel(
    const float* __restrict__ q, const float* __restrict__ k) {
    const int bx = blockIdx.x;
    const bool isq = (bx < 8192);
    const float* src = isq ? q : k;
    __half* dst = isq ? g_qh : g_kh;
    const float sc = isq ? SCALE : 1.0f;
    size_t e0 = ((size_t)(bx & 8191) * 256 + threadIdx.x) * 8;
    float4 v0 = *reinterpret_cast<const float4*>(src + e0);
    float4 v1 = *reinterpret_cast<const float4*>(src + e0 + 4);
    uint16_t h[8];
    h[0] = __half_as_ushort(__float2half_rn(v0.x * sc));
    h[1] = __half_as_ushort(__float2half_rn(v0.y * sc));
    h[2] = __half_as_ushort(__float2half_rn(v0.z * sc));
    h[3] = __half_as_ushort(__float2half_rn(v0.w * sc));
    h[4] = __half_as_ushort(__float2half_rn(v1.x * sc));
    h[5] = __half_as_ushort(__float2half_rn(v1.y * sc));
    h[6] = __half_as_ushort(__float2half_rn(v1.z * sc));
    h[7] = __half_as_ushort(__float2half_rn(v1.w * sc));
    uint2 lo = pack4(h), hi = pack4(h + 4);
    *reinterpret_cast<uint4*>(dst + e0) = make_uint4(lo.x, lo.y, hi.x, hi.y);
}

// ------------------------------ tile workers --------------------------------
__device__ __forceinline__ void v_unit(char* smg, int tid, int unit,
                                       const float* __restrict__ v) {
    float (*tile)[65] = (float(*)[65])smg;
    const int b = unit >> 6;
    const int rest0 = unit & 63;
    const int i0 = tid >> 4, j4 = (tid & 15) * 4;
#pragma unroll 1
    for (int u = 0; u < 8; ++u) {
        const int rest = rest0 * 8 + u;
        const int st = rest >> 4;
        const int dt = rest & 15;
#pragma unroll
        for (int r = 0; r < 8; ++r) {
            int i = i0 + r * 8;
            float4 val = *reinterpret_cast<const float4*>(
                v + ((size_t)b * S_ + st * 64 + i) * D_ + dt * 64 + j4);
            tile[i][j4 + 0] = val.x; tile[i][j4 + 1] = val.y;
            tile[i][j4 + 2] = val.z; tile[i][j4 + 3] = val.w;
        }
        __syncthreads();
#pragma unroll
        for (int r = 0; r < 8; ++r) {
            int dl_ = i0 + r * 8;
            uint16_t h[4];
#pragma unroll
            for (int c = 0; c < 4; ++c)
                h[c] = __half_as_ushort(__float2half_rn(tile[j4 + c][dl_]));
            size_t off = ((size_t)b * D_ + dt * 64 + dl_) * S_ + st * 64 + j4;
            *reinterpret_cast<uint2*>(g_vt + off) = pack4(h);
        }
        __syncthreads();
    }
    if (tid == 0) {
        __threadfence();
        atomicAdd(&g_sync[SY_VC0 + b], 1u);
    }
}

__device__ __forceinline__ void gemm1_tile(char* smg, uint32_t smb, int tid,
                                           int mt, int nt, int b,
                                           const __half* __restrict__ Ah,
                                           const __half* __restrict__ Bh,
                                           const float* __restrict__ mask) {
    float* smmask = (float*)(smg + OFF_MASK);
    float (*smsum)[2] = (float(*)[2])(smg + OFF_SUM);

    const int warp = tid >> 5, lane = tid & 31;
    const int wm = warp & 1, wn = warp >> 1;
    const int lrow = lane & 15;
    const int lh16 = (lane >> 4) << 4;
    const int r7 = (lane & 7) << 4;
    constexpr int NC = D_ / TK;  // 16

    const int drow = tid >> 3, cc = tid & 7;
    const uint32_t dstoff0 = (uint32_t)(drow * 128 + ((cc ^ (drow & 7)) << 4));
    const __half* gA = Ah + ((size_t)b * S_ + mt * TM + drow) * D_ + cc * 8;
    const __half* gB = Bh + ((size_t)b * S_ + nt * TN + drow) * D_ + cc * 8;

    smmask[tid] = mask[(size_t)b * S_ + nt * TN + tid] * NEGV;

    uint32_t sload = 0;
    auto issue = [&]() {
        uint32_t da = smb + sload + dstoff0;
#pragma unroll
        for (int i = 0; i < 8; ++i) {
            CP_ASYNC16(da + i * 2048,         gA + i * 16 * D_);
            CP_ASYNC16(da + BUF_B + i * 2048, gB + i * 16 * D_);
        }
        CP_COMMIT();
        gA += TK; gB += TK;
        sload += STAGE_B; if (sload == PIPE_B) sload = 0;
    };

    float acc[4][8][4];
#pragma unroll
    for (int i = 0; i < 4; ++i)
#pragma unroll
        for (int n = 0; n < 8; ++n)
#pragma unroll
            for (int r = 0; r < 4; ++r) acc[i][n][r] = 0.f;

    issue();
    issue();

    const uint32_t cA = (uint32_t)((wm * 64 + lrow) * 128);
    const uint32_t cB = (uint32_t)(BUF_B + (wn * 64 + lrow) * 128);

    uint32_t scomp = 0;
#pragma unroll 1
    for (int c = 0; c < NC; ++c) {
        if (c + 1 < NC) CP_WAIT(1);
        else            CP_WAIT(0);
        __syncthreads();
        if (c + 2 < NC) issue();

        const uint32_t uA0 = smb + scomp + cA;
        const uint32_t uB0 = smb + scomp + cB;
        scomp += STAGE_B; if (scomp == PIPE_B) scomp = 0;

        uint32_t ah[2][4][4], bh[2][4][4];
        {
            const uint32_t kxr0 = (uint32_t)(lh16 ^ r7);
#pragma unroll
            for (int i = 0; i < 4; ++i) LDSM4(ah[0][i], uA0 + i * 2048 + kxr0);
#pragma unroll
            for (int j = 0; j < 4; ++j) LDSM4(bh[0][j], uB0 + j * 2048 + kxr0);
        }
#pragma unroll
        for (int ks = 0; ks < 4; ++ks) {
            const int cur = ks & 1, nxt = cur ^ 1;
            if (ks < 3) {
                const uint32_t kxr = (uint32_t)(((ks + 1) * 32 + lh16) ^ r7);
#pragma unroll
                for (int i = 0; i < 4; ++i)
                    LDSM4(ah[nxt][i], uA0 + i * 2048 + kxr);
#pragma unroll
                for (int j = 0; j < 4; ++j)
                    LDSM4(bh[nxt][j], uB0 + j * 2048 + kxr);
            }
#pragma unroll
            for (int i = 0; i < 4; ++i)
#pragma unroll
                for (int n = 0; n < 8; ++n) {
                    int j = n >> 1, s = n & 1;
                    MMA_F16(acc[i][n], ah[cur][i], bh[cur][j][s], bh[cur][j][s + 2]);
                }
        }
    }

    const int rloc = wm * 64 + (lane >> 2);
    const int r0 = mt * TM + rloc;
    const int cl0 = wn * 64 + (lane & 3) * 2;
#pragma unroll
    for (int i = 0; i < 4; ++i) {
        float sum_lo = 0.f, sum_hi = 0.f;
#pragma unroll
        for (int n = 0; n < 8; ++n) {
            int cl = cl0 + n * 8;
            float mk0 = smmask[cl], mk1 = smmask[cl + 1];
            float e0 = __expf(acc[i][n][0] + mk0);
            float e1 = __expf(acc[i][n][1] + mk1);
            float e2 = __expf(acc[i][n][2] + mk0);
            float e3 = __expf(acc[i][n][3] + mk1);
            sum_lo += e0 + e1;
            sum_hi += e2 + e3;
            size_t rowa = (size_t)(b * S_ + r0 + i * 16) * S_ + nt * TN + cl;
            size_t rowb = rowa + (size_t)8 * S_;
            *reinterpret_cast<__half2*>(g_p + rowa) = __floats2half2_rn(e0, e1);
            *reinterpret_cast<__half2*>(g_p + rowb) = __floats2half2_rn(e2, e3);
        }
#pragma unroll
        for (int o = 1; o < 4; o <<= 1) {
            sum_lo += __shfl_xor_sync(~0u, sum_lo, o);
            sum_hi += __shfl_xor_sync(~0u, sum_hi, o);
        }
        if ((lane & 3) == 0) {
            smsum[rloc + i * 16][wn]     = sum_lo;
            smsum[rloc + i * 16 + 8][wn] = sum_hi;
        }
    }
    __syncthreads();
    g_ps[((size_t)(b * S_ + mt * TM + tid)) * 16 + nt] =
        smsum[tid][0] + smsum[tid][1];
    __syncthreads();
    if (tid == 0) {
        __threadfence();
        atomicAdd(&g_sync[SY_ROW0 + b * 16 + mt], 1u);
    }
}

__device__ __forceinline__ void gemm2_tile(char* smg, uint32_t smb, int tid,
                                           int mt, int nt, int b,
                                           float* __restrict__ Cp) {
    float* sminv = (float*)(smg + OFF_MASK);  // reuse mask slot: [128]

    // readiness: tid0 spins on row-group + V flags, then block-wide barrier.
    if (tid == 0) {
        const unsigned int* rowc = &g_sync[SY_ROW0 + b * 16 + mt];
        const unsigned int* vc   = &g_sync[SY_VC0 + b];
        while (ld_acquire(rowc) < 16u) __nanosleep(64);
        while (ld_acquire(vc) < 64u)   __nanosleep(64);
    }
    __syncthreads();

    const int warp = tid >> 5, lane = tid & 31;
    const int wm = warp & 1, wn = warp >> 1;
    const int lrow = lane & 15;
    const int lh16 = (lane >> 4) << 4;
    const int r7 = (lane & 7) << 4;
    constexpr int NC = S_ / TK;  // 32

    const int drow = tid >> 3, cc = tid & 7;
    const uint32_t dstoff0 = (uint32_t)(drow * 128 + ((cc ^ (drow & 7)) << 4));
    const __half* gA = g_p  + ((size_t)b * S_ + mt * TM + drow) * S_ + cc * 8;
    const __half* gB = g_vt + ((size_t)b * D_ + nt * TN + drow) * S_ + cc * 8;

    {
        const float* ps = g_ps + ((size_t)(b * S_ + mt * TM + tid)) * 16;
        float s = 0.f;
#pragma unroll
        for (int j = 0; j < 16; ++j) s += __ldcg(ps + j);
        sminv[tid] = 1.0f / s;
    }

    uint32_t sload = 0;
    auto issue = [&]() {
        uint32_t da = smb + sload + dstoff0;
#pragma unroll
        for (int i = 0; i < 8; ++i) {
            CP_ASYNC16(da + i * 2048,         gA + i * 16 * S_);
            CP_ASYNC16(da + BUF_B + i * 2048, gB + i * 16 * S_);
        }
        CP_COMMIT();
        gA += TK; gB += TK;
        sload += STAGE_B; if (sload == PIPE_B) sload = 0;
    };

    float acc[4][8][4];
#pragma unroll
    for (int i = 0; i < 4; ++i)
#pragma unroll
        for (int n = 0; n < 8; ++n)
#pragma unroll
            for (int r = 0; r < 4; ++r) acc[i][n][r] = 0.f;

    issue();
    issue();

    const uint32_t cA = (uint32_t)((wm * 64 + lrow) * 128);
    const uint32_t cB = (uint32_t)(BUF_B + (wn * 64 + lrow) * 128);

    uint32_t scomp = 0;
#pragma unroll 1
    for (int c = 0; c < NC; ++c) {
        if (c + 1 < NC) CP_WAIT(1);
        else            CP_WAIT(0);
        __syncthreads();
        if (c + 2 < NC) issue();

        const uint32_t uA0 = smb + scomp + cA;
        const uint32_t uB0 = smb + scomp + cB;
        scomp += STAGE_B; if (scomp == PIPE_B) scomp = 0;

        uint32_t ah[2][4][4], bh[2][4][4];
        {
            const uint32_t kxr0 = (uint32_t)(lh16 ^ r7);
#pragma unroll
            for (int i = 0; i < 4; ++i) LDSM4(ah[0][i], uA0 + i * 2048 + kxr0);
#pragma unroll
            for (int j = 0; j < 4; ++j) LDSM4(bh[0][j], uB0 + j * 2048 + kxr0);
        }
#pragma unroll
        for (int ks = 0; ks < 4; ++ks) {
            const int cur = ks & 1, nxt = cur ^ 1;
            if (ks < 3) {
                const uint32_t kxr = (uint32_t)(((ks + 1) * 32 + lh16) ^ r7);
#pragma unroll
                for (int i = 0; i < 4; ++i)
                    LDSM4(ah[nxt][i], uA0 + i * 2048 + kxr);
#pragma unroll
                for (int j = 0; j < 4; ++j)
                    LDSM4(bh[nxt][j], uB0 + j * 2048 + kxr);
            }
#pragma unroll
            for (int i = 0; i < 4; ++i)
#pragma unroll
                for (int n = 0; n < 8; ++n) {
                    int j = n >> 1, s = n & 1;
                    MMA_F16(acc[i][n], ah[cur][i], bh[cur][j][s], bh[cur][j][s + 2]);
                }
        }
    }

    const int rloc = wm * 64 + (lane >> 2);
    const int r0 = mt * TM + rloc;
    const int cl0 = wn * 64 + (lane & 3) * 2;
#pragma unroll
    for (int i = 0; i < 4; ++i) {
        float inv_lo = sminv[rloc + i * 16];
        float inv_hi = sminv[rloc + i * 16 + 8];
#pragma unroll
        for (int n = 0; n < 8; ++n) {
            int col = nt * TN + cl0 + n * 8;
            size_t rowa = (size_t)(b * S_ + r0 + i * 16) * D_ + col;
            size_t rowb = rowa + (size_t)8 * D_;
            *reinterpret_cast<float2*>(Cp + rowa) =
                make_float2(acc[i][n][0] * inv_lo, acc[i][n][1] * inv_lo);
            *reinterpret_cast<float2*>(Cp + rowb) =
                make_float2(acc[i][n][2] * inv_hi, acc[i][n][3] * inv_hi);
        }
    }
}

// ------------------------- fused persistent kernel ---------------------------
__global__ void __launch_bounds__(NT, 2)
attn_fused_kernel(const __half* __restrict__ Ah, const __half* __restrict__ Bh,
                  const float* __restrict__ mask, const float* __restrict__ v,
                  float* __restrict__ out) {
    extern __shared__ __align__(1024) char smg[];
    const uint32_t smb = smem_u32(smg);
    const int tid = threadIdx.x;
    volatile unsigned int* spop = (volatile unsigned int*)(smg + OFF_POP);

    // ---- phase 1: V units, then gemm1 tiles ----
    for (;;) {
        __syncthreads();                 // smem reuse guard + pop broadcast
        if (tid == 0) *spop = atomicAdd(&g_sync[SY_TIX1], 1u);
        __syncthreads();
        unsigned int t = *spop;
        if (t >= PH1_TOTAL) break;
        if (t < PH1_V) {
            v_unit(smg, tid, (int)t, v);
        } else {
            const int g = (int)t - PH1_V;
            const int rg = g >> 4, nt = g & 15;
            const int b = rg >> 4, mt = rg & 15;
            gemm1_tile(smg, smb, tid, mt, nt, b, Ah, Bh, mask);
        }
    }

    // ---- phase 2: gemm2 tiles ----
    for (;;) {
        __syncthreads();
        if (tid == 0) *spop = atomicAdd(&g_sync[SY_TIX2], 1u);
        __syncthreads();
        unsigned int t = *spop;
        if (t >= PH2_TOTAL) break;
        const int rg = (int)t >> 3, nt = (int)t & 7;
        const int b = rg >> 4, mt = rg & 15;
        gemm2_tile(smg, smb, tid, mt, nt, b, out);
    }
}

// --------------------------------- launch -----------------------------------
extern "C" void kernel_launch(void* const* d_in, const int* in_sizes, int n_in,
                              void* d_out, int out_size) {
    const float* q    = (const float*)d_in[0];
    const float* k    = (const float*)d_in[1];
    const float* v    = (const float*)d_in[2];
    const float* mask = (const float*)d_in[3];
    float* out = (float*)d_out;

    cudaFuncSetAttribute(attn_fused_kernel,
                         cudaFuncAttributeMaxDynamicSharedMemorySize, SMEM_F);

    __half *qh, *kh;
    void* syncp;
    cudaGetSymbolAddress((void**)&qh, g_qh);
    cudaGetSymbolAddress((void**)&kh, g_kh);
    cudaGetSymbolAddress(&syncp, g_sync);

    int nsm = 148;
    cudaDeviceGetAttribute(&nsm, cudaDevAttrMultiProcessorCount, 0);

    cudaMemsetAsync(syncp, 0, SY_N * sizeof(unsigned int));
    conv_qk_kernel<<<16384, 256>>>(q, k);
    attn_fused_kernel<<<2 * nsm, NT, SMEM_F>>>(qh, kh, mask, v, out);
}